// round 10
// baseline (speedup 1.0000x reference)
#include <cuda_runtime.h>
#include <cuda_fp16.h>
#include <math.h>
#include <stdint.h>

// NT-Xent R10: fused persistent kernel, 148 CTAs x 1024 threads (32 warps/SM,
// occ 50% vs 25% in R9 — profile showed latency-bound, nothing saturated).
// Warp tile 32x32 (acc 16 regs) to fit 64 regs/thread. CTA tile 128x256 over
// the upper triangle (1056 tiles), fp16 HMMA, exact fp32 positive logits.

#define TWO_N   8192
#define N_HALF  4096
#define CDIM    128
#define NBLK    64
#define TILES   1056
#define GRID    148
#define INV_T   14.285714285714286f
#define K1      20.60984248218323f           // INV_T * log2(e)

#define TSTRIDE 272
#define A_BYTES (128 * TSTRIDE)
#define B_BYTES (256 * TSTRIDE)
#define OFF_A0  0
#define OFF_A1  A_BYTES
#define OFF_B0  (2 * A_BYTES)
#define OFF_B1  (2 * A_BYTES + B_BYTES)
#define OFF_RED (2 * A_BYTES + 2 * B_BYTES)  // 208896
#define SMEM_DYN (OFF_RED + 128 * 9 * 4 + 256 * 4 * 4)   // 217600

__device__ __align__(16) __half g_Fh[TWO_N * CDIM];
__device__ float g_part[NBLK * NBLK * 128];
__device__ float g_pos[TWO_N];
__device__ double g_bsum[8];
__device__ int g_ctr;
__device__ int g_sense;
__device__ int g_count;

__device__ __forceinline__ uint32_t smem_u32(const void* p) {
    uint32_t a;
    asm("{ .reg .u64 t; cvta.to.shared.u64 t, %1; cvt.u32.u64 %0, t; }"
        : "=r"(a) : "l"(p));
    return a;
}
__device__ __forceinline__ float ex2f(float x) {
    float r;
    asm("ex2.approx.ftz.f32 %0, %1;" : "=f"(r) : "f"(x));
    return r;
}
__device__ __forceinline__ void cp16(uint32_t s, const void* g) {
    asm volatile("cp.async.cg.shared.global [%0], [%1], 16;" :: "r"(s), "l"(g));
}
#define CP_COMMIT() asm volatile("cp.async.commit_group;" ::: "memory")
#define CP_WAIT1()  asm volatile("cp.async.wait_group 1;" ::: "memory")
#define CP_WAIT0()  asm volatile("cp.async.wait_group 0;" ::: "memory")

#define LDSM_X4(r0, r1, r2, r3, addr)                                          \
    asm volatile("ldmatrix.sync.aligned.m8n8.x4.shared.b16 {%0,%1,%2,%3},[%4];"\
        : "=r"(r0), "=r"(r1), "=r"(r2), "=r"(r3) : "r"(addr))

#define MMA16816H(c, a, b0, b1)                                                \
    asm volatile("mma.sync.aligned.m16n8k16.row.col.f16.f16.f16.f16 "          \
        "{%0,%1},{%2,%3,%4,%5},{%6,%7},{%0,%1};"                               \
        : "+r"((c)[0]), "+r"((c)[1])                                           \
        : "r"((a)[0]), "r"((a)[1]), "r"((a)[2]), "r"((a)[3]),                  \
          "r"(b0), "r"(b1))

__device__ __forceinline__ void gbar(int tid, int& target) {
    __syncthreads();
    if (tid == 0) {
        __threadfence();
        if (atomicAdd(&g_count, 1) == GRID - 1) {
            g_count = 0;
            __threadfence();
            atomicAdd(&g_sense, 1);
        } else {
            while (((volatile int*)&g_sense)[0] - target < 0) {}
            __threadfence();
        }
    }
    __syncthreads();
    target++;
}

extern __shared__ char dynsmem[];

__global__ void __launch_bounds__(1024, 1) ntxent_fused_kernel(
        const float* __restrict__ f1, const float* __restrict__ f2,
        float* __restrict__ out) {
    const int tid  = threadIdx.x;
    const int lane = tid & 31;
    const int wid  = tid >> 5;       // 0..31
    const int wm   = wid & 3;        // 4 m-warps of 32 rows
    const int wn   = wid >> 2;       // 8 n-warps of 32 cols
    const int bx   = blockIdx.x;

    __shared__ int sTgt;
    if (tid == 0) sTgt = ((volatile int*)&g_sense)[0] + 1;
    __syncthreads();
    int target = sTgt;

    // ---------------- Phase A: normalize + pos logits ----------------
    {
        int i = bx * 32 + wid;
        if (i < N_HALF) {
            float4 a = *(const float4*)(f1 + (size_t)i * CDIM + lane * 4);
            float4 b = *(const float4*)(f2 + (size_t)i * CDIM + lane * 4);
            float s1 = a.x * a.x + a.y * a.y + a.z * a.z + a.w * a.w;
            float s2 = b.x * b.x + b.y * b.y + b.z * b.z + b.w * b.w;
            float d  = a.x * b.x + a.y * b.y + a.z * b.z + a.w * b.w;
            #pragma unroll
            for (int o = 16; o; o >>= 1) {
                s1 += __shfl_xor_sync(0xffffffffu, s1, o);
                s2 += __shfl_xor_sync(0xffffffffu, s2, o);
                d  += __shfl_xor_sync(0xffffffffu, d,  o);
            }
            float i1 = 1.0f / fmaxf(sqrtf(s1), 1e-12f);
            float i2 = 1.0f / fmaxf(sqrtf(s2), 1e-12f);

            __half2 h0 = __floats2half2_rn(a.x * i1, a.y * i1);
            __half2 h1 = __floats2half2_rn(a.z * i1, a.w * i1);
            uint2 u;
            u.x = *(uint32_t*)&h0; u.y = *(uint32_t*)&h1;
            *(uint2*)(g_Fh + (size_t)i * CDIM + lane * 4) = u;

            __half2 g0 = __floats2half2_rn(b.x * i2, b.y * i2);
            __half2 g1 = __floats2half2_rn(b.z * i2, b.w * i2);
            u.x = *(uint32_t*)&g0; u.y = *(uint32_t*)&g1;
            *(uint2*)(g_Fh + (size_t)(i + N_HALF) * CDIM + lane * 4) = u;

            if (lane == 0) {
                float pos = (d * i1 * i2 - 1.0f) * INV_T;
                g_pos[i] = pos;
                g_pos[i + N_HALF] = pos;
            }
        }
    }

    gbar(tid, target);

    // ---------------- Phase B: HMMA triangle tiles ----------------
    {
        uint32_t sb = smem_u32(dynsmem);
        const uint32_t bufA[2] = { sb + OFF_A0, sb + OFF_A1 };
        const uint32_t bufB[2] = { sb + OFF_B0, sb + OFF_B1 };
        float* sRow = (float*)(dynsmem + OFF_RED);       // [128][9]
        float* sCol = sRow + 128 * 9;                    // [256][4]

        // A: rows wm*32 + mi*16 + (lane&15); B: rows = cols wn*32 + ...
        const uint32_t aSel = (uint32_t)((wm * 32 + (lane & 15)) * TSTRIDE)
                            + (uint32_t)((lane >> 4) * 16);
        const uint32_t bSel = (uint32_t)((wn * 32 + (lane & 7) + ((lane >> 4) & 1) * 8) * TSTRIDE)
                            + (uint32_t)(((lane >> 3) & 1) * 16);

        auto mapIJ = [](int k, int& I, int& J2) {
            int i = 0, rem = k;
            while (rem >= 32 - (i >> 1)) { rem -= 32 - (i >> 1); i++; }
            I = i; J2 = (i >> 1) + rem;
        };
        auto issue_tile = [&](int I, int J2, int buf) {
            const char* gA = (const char*)(g_Fh + ((size_t)I << 7) * CDIM);
            const char* gB = (const char*)(g_Fh + ((size_t)J2 << 8) * CDIM);
            #pragma unroll
            for (int i = 0; i < 2; i++) {
                int idx = tid + i * 1024, r = idx >> 4, c = idx & 15;
                cp16(bufA[buf] + r * TSTRIDE + c * 16, gA + r * 256 + c * 16);
            }
            #pragma unroll
            for (int i = 0; i < 4; i++) {
                int idx = tid + i * 1024, r = idx >> 4, c = idx & 15;
                cp16(bufB[buf] + r * TSTRIDE + c * 16, gB + r * 256 + c * 16);
            }
            CP_COMMIT();
        };

        auto compute_tile = [&](int cur, int I, int J2) {
            const int Jblk = 2 * J2 + (wn >> 2);
            const bool active = (Jblk >= I);
            float pr[4], pc[8];
            #pragma unroll
            for (int h = 0; h < 4; h++) pr[h] = 0.f;
            #pragma unroll
            for (int h = 0; h < 8; h++) pc[h] = 0.f;

            if (active) {
                uint32_t acc[2][4][2];
                #pragma unroll
                for (int mi = 0; mi < 2; mi++)
                    #pragma unroll
                    for (int ni = 0; ni < 4; ni++) {
                        acc[mi][ni][0] = 0u; acc[mi][ni][1] = 0u;
                    }
                const uint32_t aT = bufA[cur] + aSel;
                const uint32_t bT = bufB[cur] + bSel;
                #pragma unroll
                for (int ks = 0; ks < 8; ks++) {
                    uint32_t afr[2][4], bfr[2][4];
                    #pragma unroll
                    for (int mi = 0; mi < 2; mi++) {
                        uint32_t ad = aT + (uint32_t)(mi * 16 * TSTRIDE + ks * 32);
                        LDSM_X4(afr[mi][0], afr[mi][1], afr[mi][2], afr[mi][3], ad);
                    }
                    #pragma unroll
                    for (int np = 0; np < 2; np++) {
                        uint32_t bd = bT + (uint32_t)(np * 16 * TSTRIDE + ks * 32);
                        LDSM_X4(bfr[np][0], bfr[np][1], bfr[np][2], bfr[np][3], bd);
                    }
                    #pragma unroll
                    for (int mi = 0; mi < 2; mi++)
                        #pragma unroll
                        for (int ni = 0; ni < 4; ni++)
                            MMA16816H(acc[mi][ni], afr[mi],
                                      bfr[ni >> 1][(ni & 1) * 2],
                                      bfr[ni >> 1][(ni & 1) * 2 + 1]);
                }
                #pragma unroll
                for (int mi = 0; mi < 2; mi++)
                    #pragma unroll
                    for (int ni = 0; ni < 4; ni++)
                        #pragma unroll
                        for (int rg = 0; rg < 2; rg++) {
                            float2 f = __half22float2(
                                *(const __half2*)&acc[mi][ni][rg]);
                            float e0 = ex2f(fmaf(f.x, K1, -K1));
                            float e1 = ex2f(fmaf(f.y, K1, -K1));
                            pr[mi * 2 + rg] += e0 + e1;
                            pc[ni * 2]     += e0;
                            pc[ni * 2 + 1] += e1;
                        }
                if (Jblk == I) {
                    #pragma unroll
                    for (int mi = 0; mi < 2; mi++)
                        #pragma unroll
                        for (int ni = 0; ni < 4; ni++)
                            #pragma unroll
                            for (int rg = 0; rg < 2; rg++) {
                                int rT = wm * 32 + mi * 16 + (lane >> 2) + 8 * rg;
                                int cB = (wn & 3) * 32 + ni * 8 + (lane & 3) * 2;
                                if (cB == rT || cB + 1 == rT) {
                                    float2 f = __half22float2(
                                        *(const __half2*)&acc[mi][ni][rg]);
                                    float fd = (cB == rT) ? f.x : f.y;
                                    pr[mi * 2 + rg] -= ex2f(fmaf(fd, K1, -K1));
                                }
                            }
                }
            }

            #pragma unroll
            for (int h = 0; h < 4; h++) {
                pr[h] += __shfl_xor_sync(0xffffffffu, pr[h], 1);
                pr[h] += __shfl_xor_sync(0xffffffffu, pr[h], 2);
            }
            #pragma unroll
            for (int h = 0; h < 8; h++) {
                pc[h] += __shfl_xor_sync(0xffffffffu, pc[h], 4);
                pc[h] += __shfl_xor_sync(0xffffffffu, pc[h], 8);
                pc[h] += __shfl_xor_sync(0xffffffffu, pc[h], 16);
            }
            if ((lane & 3) == 0) {
                #pragma unroll
                for (int h = 0; h < 4; h++) {
                    int r = wm * 32 + (h >> 1) * 16 + (lane >> 2) + 8 * (h & 1);
                    sRow[r * 9 + wn] = pr[h];
                }
            }
            if (lane < 4) {
                #pragma unroll
                for (int h = 0; h < 8; h++) {
                    int c = wn * 32 + (h >> 1) * 8 + lane * 2 + (h & 1);
                    sCol[c * 4 + wm] = pc[h];
                }
            }
            __syncthreads();   // reductions visible; buf cur reads done

            const int JA = 2 * J2, JB = 2 * J2 + 1;
            if (tid < 128) {
                float vA = sRow[tid * 9 + 0] + sRow[tid * 9 + 1]
                         + sRow[tid * 9 + 2] + sRow[tid * 9 + 3];
                float vB = sRow[tid * 9 + 4] + sRow[tid * 9 + 5]
                         + sRow[tid * 9 + 6] + sRow[tid * 9 + 7];
                if (JA >= I) g_part[((size_t)I * NBLK + JA) * 128 + tid] = vA;
                g_part[((size_t)I * NBLK + JB) * 128 + tid] = vB;
            } else if (tid < 384) {
                int c  = tid - 128;
                int Jb = JA + (c >> 7);
                if (Jb > I)
                    g_part[((size_t)Jb * NBLK + I) * 128 + (c & 127)] =
                        sCol[c * 4] + sCol[c * 4 + 1] + sCol[c * 4 + 2] + sCol[c * 4 + 3];
            }
        };

        int k = bx;
        int I, J2, In, Jn;
        mapIJ(k, I, J2);
        issue_tile(I, J2, 0);
        int k1 = k + GRID;
        bool h1 = (k1 < TILES);
        if (h1) { mapIJ(k1, In, Jn); issue_tile(In, Jn, 1); CP_WAIT1(); }
        else    { CP_WAIT0(); }
        __syncthreads();

        int t = 0;
        while (true) {
            int cur = t & 1;
            compute_tile(cur, I, J2);
            if (k + GRID >= TILES) break;
            int k2 = k + 2 * GRID;
            int In2 = 0, Jn2 = 0;
            if (k2 < TILES) {
                mapIJ(k2, In2, Jn2);
                issue_tile(In2, Jn2, cur);
                CP_WAIT1();
            } else {
                CP_WAIT0();
            }
            __syncthreads();
            I = In; J2 = Jn; In = In2; Jn = Jn2;
            k += GRID; t++;
        }
    }

    gbar(tid, target);

    // ---------------- Phase C: gather + final reduction ----------------
    if (bx < 8) {
        double* sm = (double*)dynsmem;
        int row = bx * 1024 + tid;
        int R = row >> 7, m = row & 127;
        float s = 0.f;
        #pragma unroll 8
        for (int O = 0; O < NBLK; O++)
            s += g_part[((size_t)R * NBLK + O) * 128 + m];
        sm[tid] = (double)(g_pos[row] - logf(s));
        __syncthreads();
        #pragma unroll
        for (int o = 512; o; o >>= 1) {
            if (tid < o) sm[tid] += sm[tid + o];
            __syncthreads();
        }
        __shared__ int isLast;
        if (tid == 0) {
            g_bsum[bx] = sm[0];
            __threadfence();
            isLast = (atomicAdd(&g_ctr, 1) == 7);
        }
        __syncthreads();
        if (isLast && tid == 0) {
            double tot = 0.0;
            #pragma unroll
            for (int i = 0; i < 8; i++) tot += g_bsum[i];
            out[0] = (float)(-tot / (double)TWO_N);
            g_ctr = 0;   // reset for graph replay
        }
    }
}

// ---------------------------------------------------------------------------
extern "C" void kernel_launch(void* const* d_in, const int* in_sizes, int n_in,
                              void* d_out, int out_size) {
    const float* f1 = (const float*)d_in[0];
    const float* f2 = (const float*)d_in[1];
    float* out = (float*)d_out;

    cudaFuncSetAttribute(ntxent_fused_kernel,
                         cudaFuncAttributeMaxDynamicSharedMemorySize, SMEM_DYN);

    ntxent_fused_kernel<<<GRID, 1024, SMEM_DYN>>>(f1, f2, out);
}

// round 11
// speedup vs baseline: 1.2378x; 1.2378x over previous
#include <cuda_runtime.h>
#include <cuda_fp16.h>
#include <math.h>
#include <stdint.h>

// NT-Xent R11: kill the load-issue bottleneck (R10 profile: 6144 cp.async/tile
// ~= 12k cyc/SMSP vs 4k MMA). One cp.async.bulk per 32KB block; g_Fs stored
// pre-swizzled per 128-row block so linear bulk copy is ldmatrix-conflict-free.
// Contiguous triangle ranges per CTA (A block reused across tiles). 148 CTAs
// x 512 thr, fused phases with global barriers.

#define TWO_N   8192
#define N_HALF  4096
#define CDIM    128
#define NBLK    64
#define TILES   2080                         // 64*65/2, 128x128 tiles
#define GRID    148
#define INV_T   14.285714285714286f
#define K1      20.60984248218323f           // INV_T * log2(e)
#define BLKB    32768                        // one 128-row block, fp16

#define OFF_A0  0
#define OFF_A1  BLKB
#define OFF_B0  (2 * BLKB)
#define OFF_B1  (3 * BLKB)
#define OFF_RED (4 * BLKB)                   // 131072
#define SMEM_DYN (OFF_RED + 128 * 5 * 4 * 2) // 136192

__device__ __align__(128) __half g_Fs[TWO_N * CDIM];   // swizzled blocks
__device__ float g_part[NBLK * NBLK * 128];
__device__ float g_pos[TWO_N];
__device__ double g_bsum[16];
__device__ int g_ctr;
__device__ int g_sense;
__device__ int g_count;

__device__ __forceinline__ uint32_t smem_u32(const void* p) {
    uint32_t a;
    asm("{ .reg .u64 t; cvta.to.shared.u64 t, %1; cvt.u32.u64 %0, t; }"
        : "=r"(a) : "l"(p));
    return a;
}
__device__ __forceinline__ float ex2f(float x) {
    float r;
    asm("ex2.approx.ftz.f32 %0, %1;" : "=f"(r) : "f"(x));
    return r;
}
__device__ __forceinline__ void bulk_cp(uint32_t s, const void* g,
                                        uint32_t bytes, uint32_t mbar) {
    asm volatile(
        "cp.async.bulk.shared::cta.global.mbarrier::complete_tx::bytes "
        "[%0], [%1], %2, [%3];"
        :: "r"(s), "l"(g), "r"(bytes), "r"(mbar) : "memory");
}
#define MBAR_INIT(a, n) \
    asm volatile("mbarrier.init.shared.b64 [%0], %1;" :: "r"(a), "r"(n) : "memory")
#define MBAR_EXPECT(a, bytes) \
    asm volatile("mbarrier.arrive.expect_tx.shared.b64 _, [%0], %1;" \
                 :: "r"(a), "r"((uint32_t)(bytes)) : "memory")
#define MBAR_WAIT(a, ph) do {                                                  \
    uint32_t _m = (a), _p = (ph), _d;                                          \
    asm volatile("{\n\t.reg .pred p;\n\t"                                      \
        "mbarrier.try_wait.parity.acquire.cta.shared::cta.b64 p, [%1], %2;\n\t"\
        "selp.b32 %0, 1, 0, p;\n\t}"                                           \
        : "=r"(_d) : "r"(_m), "r"(_p) : "memory");                             \
    if (!_d) {                                                                 \
        asm volatile("{\n\t.reg .pred P1;\n\t"                                 \
            "W%=:\n\t"                                                         \
            "mbarrier.try_wait.parity.acquire.cta.shared::cta.b64 P1, [%0], %1, 0x989680;\n\t" \
            "@P1 bra.uni D%=;\n\t"                                             \
            "bra.uni W%=;\n\t"                                                 \
            "D%=:\n\t}" :: "r"(_m), "r"(_p) : "memory");                       \
    } } while (0)
#define FENCE_PROXY() asm volatile("fence.proxy.async;" ::: "memory")

#define LDSM_X4(r0, r1, r2, r3, addr)                                          \
    asm volatile("ldmatrix.sync.aligned.m8n8.x4.shared.b16 {%0,%1,%2,%3},[%4];"\
        : "=r"(r0), "=r"(r1), "=r"(r2), "=r"(r3) : "r"(addr))

#define MMA16816H(c, a, b0, b1)                                                \
    asm volatile("mma.sync.aligned.m16n8k16.row.col.f16.f16.f16.f16 "          \
        "{%0,%1},{%2,%3,%4,%5},{%6,%7},{%0,%1};"                               \
        : "+r"((c)[0]), "+r"((c)[1])                                           \
        : "r"((a)[0]), "r"((a)[1]), "r"((a)[2]), "r"((a)[3]),                  \
          "r"(b0), "r"(b1))

__device__ __forceinline__ void gbar(int tid, int& target) {
    __syncthreads();
    if (tid == 0) {
        __threadfence();
        if (atomicAdd(&g_count, 1) == GRID - 1) {
            g_count = 0;
            __threadfence();
            atomicAdd(&g_sense, 1);
        } else {
            while (((volatile int*)&g_sense)[0] - target < 0) {}
            __threadfence();
        }
    }
    __syncthreads();
    target++;
}

extern __shared__ char dynsmem[];

__global__ void __launch_bounds__(512, 1) ntxent_fused_kernel(
        const float* __restrict__ f1, const float* __restrict__ f2,
        float* __restrict__ out) {
    const int tid  = threadIdx.x;
    const int lane = tid & 31;
    const int wid  = tid >> 5;       // 0..15
    const int wm   = wid & 3;        // 4 m-warps x 32 rows
    const int wn   = wid >> 2;       // 4 n-warps x 32 cols
    const int bx   = blockIdx.x;

    __shared__ __align__(8) uint64_t s_mbar[2];
    __shared__ int sTgt;
    const uint32_t mb[2] = { smem_u32(&s_mbar[0]), smem_u32(&s_mbar[1]) };

    if (tid == 0) {
        sTgt = ((volatile int*)&g_sense)[0] + 1;
        MBAR_INIT(mb[0], 1);
        MBAR_INIT(mb[1], 1);
        FENCE_PROXY();
    }
    __syncthreads();
    int target = sTgt;

    // ---------------- Phase A: normalize + swizzled fp16 + pos ----------------
    for (int i = bx * 16 + wid; i < N_HALF; i += GRID * 16) {
        float4 a = *(const float4*)(f1 + (size_t)i * CDIM + lane * 4);
        float4 b = *(const float4*)(f2 + (size_t)i * CDIM + lane * 4);
        float s1 = a.x * a.x + a.y * a.y + a.z * a.z + a.w * a.w;
        float s2 = b.x * b.x + b.y * b.y + b.z * b.z + b.w * b.w;
        float d  = a.x * b.x + a.y * b.y + a.z * b.z + a.w * b.w;
        #pragma unroll
        for (int o = 16; o; o >>= 1) {
            s1 += __shfl_xor_sync(0xffffffffu, s1, o);
            s2 += __shfl_xor_sync(0xffffffffu, s2, o);
            d  += __shfl_xor_sync(0xffffffffu, d,  o);
        }
        float i1 = 1.0f / fmaxf(sqrtf(s1), 1e-12f);
        float i2 = 1.0f / fmaxf(sqrtf(s2), 1e-12f);

        // swizzled offset for 8B piece: chunk c16 = lane>>1, half = lane&1
        int c16 = lane >> 1, hf = lane & 1;
        {
            int r = i & 127;
            uint32_t off = (uint32_t)(i >> 7) * BLKB + (uint32_t)r * 256
                         + (uint32_t)((c16 ^ (r & 7)) * 16) + (uint32_t)hf * 8;
            __half2 h0 = __floats2half2_rn(a.x * i1, a.y * i1);
            __half2 h1 = __floats2half2_rn(a.z * i1, a.w * i1);
            uint2 u; u.x = *(uint32_t*)&h0; u.y = *(uint32_t*)&h1;
            *(uint2*)((char*)g_Fs + off) = u;
        }
        {
            int j = i + N_HALF;
            int r = j & 127;
            uint32_t off = (uint32_t)(j >> 7) * BLKB + (uint32_t)r * 256
                         + (uint32_t)((c16 ^ (r & 7)) * 16) + (uint32_t)hf * 8;
            __half2 g0 = __floats2half2_rn(b.x * i2, b.y * i2);
            __half2 g1 = __floats2half2_rn(b.z * i2, b.w * i2);
            uint2 u; u.x = *(uint32_t*)&g0; u.y = *(uint32_t*)&g1;
            *(uint2*)((char*)g_Fs + off) = u;
        }
        if (lane == 0) {
            float pos = (d * i1 * i2 - 1.0f) * INV_T;
            g_pos[i] = pos;
            g_pos[i + N_HALF] = pos;
        }
    }

    gbar(tid, target);
    FENCE_PROXY();   // generic g_Fs writes -> async-proxy bulk reads

    // ---------------- Phase B: HMMA tiles via bulk-copied blocks ----------------
    {
        uint32_t sb = smem_u32(dynsmem);
        const uint32_t bufA[2] = { sb + OFF_A0, sb + OFF_A1 };
        const uint32_t bufB[2] = { sb + OFF_B0, sb + OFF_B1 };
        float* sRow = (float*)(dynsmem + OFF_RED);   // [128][5]
        float* sCol = sRow + 128 * 5;                // [128][5]

        // Per-thread fragment address components (swizzled layout).
        const int rowA  = wm * 32 + (lane & 15);
        const int r7A   = rowA & 7;
        const int cbA   = lane >> 4;                 // chunk low bit
        const uint32_t aRB = (uint32_t)rowA * 256;
        const int rlowB = (lane & 7) + ((lane >> 4) & 1) * 8;
        const int rowB  = wn * 32 + rlowB;
        const int r7B   = rowB & 7;
        const int cbB   = (lane >> 3) & 1;
        const uint32_t bRB = (uint32_t)rowB * 256;

        auto compute_tile = [&](uint32_t aBuf, uint32_t bBuf, int I, int J) {
            float pr[4], pc[8];
            #pragma unroll
            for (int h = 0; h < 4; h++) pr[h] = 0.f;
            #pragma unroll
            for (int h = 0; h < 8; h++) pc[h] = 0.f;

            uint32_t acc[2][4][2];
            #pragma unroll
            for (int mi = 0; mi < 2; mi++)
                #pragma unroll
                for (int ni = 0; ni < 4; ni++) {
                    acc[mi][ni][0] = 0u; acc[mi][ni][1] = 0u;
                }
            #pragma unroll
            for (int ks = 0; ks < 8; ks++) {
                uint32_t afr[2][4], bfr[2][4];
                const uint32_t aoff = (uint32_t)(((ks * 2 + cbA) ^ r7A) * 16);
                const uint32_t boff = (uint32_t)(((ks * 2 + cbB) ^ r7B) * 16);
                #pragma unroll
                for (int mi = 0; mi < 2; mi++) {
                    uint32_t ad = aBuf + aRB + (uint32_t)(mi * 16 * 256) + aoff;
                    LDSM_X4(afr[mi][0], afr[mi][1], afr[mi][2], afr[mi][3], ad);
                }
                #pragma unroll
                for (int np = 0; np < 2; np++) {
                    uint32_t bd = bBuf + bRB + (uint32_t)(np * 16 * 256) + boff;
                    LDSM_X4(bfr[np][0], bfr[np][1], bfr[np][2], bfr[np][3], bd);
                }
                #pragma unroll
                for (int mi = 0; mi < 2; mi++)
                    #pragma unroll
                    for (int ni = 0; ni < 4; ni++)
                        MMA16816H(acc[mi][ni], afr[mi],
                                  bfr[ni >> 1][(ni & 1) * 2],
                                  bfr[ni >> 1][(ni & 1) * 2 + 1]);
            }
            #pragma unroll
            for (int mi = 0; mi < 2; mi++)
                #pragma unroll
                for (int ni = 0; ni < 4; ni++)
                    #pragma unroll
                    for (int rg = 0; rg < 2; rg++) {
                        float2 f = __half22float2(*(const __half2*)&acc[mi][ni][rg]);
                        float e0 = ex2f(fmaf(f.x, K1, -K1));
                        float e1 = ex2f(fmaf(f.y, K1, -K1));
                        pr[mi * 2 + rg] += e0 + e1;
                        pc[ni * 2]     += e0;
                        pc[ni * 2 + 1] += e1;
                    }
            if (I == J) {
                #pragma unroll
                for (int mi = 0; mi < 2; mi++)
                    #pragma unroll
                    for (int ni = 0; ni < 4; ni++)
                        #pragma unroll
                        for (int rg = 0; rg < 2; rg++) {
                            int rT = wm * 32 + mi * 16 + (lane >> 2) + 8 * rg;
                            int cB = wn * 32 + ni * 8 + (lane & 3) * 2;
                            if (cB == rT || cB + 1 == rT) {
                                float2 f = __half22float2(
                                    *(const __half2*)&acc[mi][ni][rg]);
                                float fd = (cB == rT) ? f.x : f.y;
                                pr[mi * 2 + rg] -= ex2f(fmaf(fd, K1, -K1));
                            }
                        }
            }

            #pragma unroll
            for (int h = 0; h < 4; h++) {
                pr[h] += __shfl_xor_sync(0xffffffffu, pr[h], 1);
                pr[h] += __shfl_xor_sync(0xffffffffu, pr[h], 2);
            }
            #pragma unroll
            for (int h = 0; h < 8; h++) {
                pc[h] += __shfl_xor_sync(0xffffffffu, pc[h], 4);
                pc[h] += __shfl_xor_sync(0xffffffffu, pc[h], 8);
                pc[h] += __shfl_xor_sync(0xffffffffu, pc[h], 16);
            }
            if ((lane & 3) == 0) {
                #pragma unroll
                for (int h = 0; h < 4; h++) {
                    int r = wm * 32 + (h >> 1) * 16 + (lane >> 2) + 8 * (h & 1);
                    sRow[r * 5 + wn] = pr[h];
                }
            }
            if (lane < 4) {
                #pragma unroll
                for (int h = 0; h < 8; h++) {
                    int c = wn * 32 + (h >> 1) * 8 + lane * 2 + (h & 1);
                    sCol[c * 5 + wm] = pc[h];
                }
            }
            __syncthreads();
            if (tid < 128) {
                float rs = sRow[tid * 5] + sRow[tid * 5 + 1]
                         + sRow[tid * 5 + 2] + sRow[tid * 5 + 3];
                g_part[((size_t)I * NBLK + J) * 128 + tid] = rs;
            } else if (tid < 256) {
                int c = tid - 128;
                if (J > I)
                    g_part[((size_t)J * NBLK + I) * 128 + c] =
                        sCol[c * 5] + sCol[c * 5 + 1] + sCol[c * 5 + 2] + sCol[c * 5 + 3];
            }
            __syncthreads();   // writeout done; buffers reusable
        };

        // Contiguous tile range for this CTA.
        const int s = (int)(((long long)bx * TILES) / GRID);
        const int e = (int)(((long long)(bx + 1) * TILES) / GRID);
        int I = 0, rem = s;
        while (rem >= NBLK - I) { rem -= NBLK - I; I++; }
        int J = I + rem;
        const int nt = e - s;

        int ph[2] = { 0, 0 };
        int aslot = 0;
        if (tid == 0) {
            MBAR_EXPECT(mb[0], 2 * BLKB);
            bulk_cp(bufA[0], (const char*)g_Fs + (size_t)I * BLKB, BLKB, mb[0]);
            bulk_cp(bufB[0], (const char*)g_Fs + (size_t)J * BLKB, BLKB, mb[0]);
        }

        int cI = I, cJ = J;          // tile t coords
        int ca = 0;                  // A slot of tile t
        for (int t = 0; t < nt; t++) {
            const int cur = t & 1;
            MBAR_WAIT(mb[cur], ph[cur]); ph[cur] ^= 1;

            if (t + 1 < nt) {
                int pI = cI, pJ = cJ + 1;
                if (pJ == NBLK) { pI = cI + 1; pJ = pI; }
                int nslot = (pI != cI) ? (ca ^ 1) : ca;
                if (tid == 0) {
                    uint32_t bytes = (pI != cI) ? 2 * BLKB : BLKB;
                    MBAR_EXPECT(mb[cur ^ 1], bytes);
                    if (pI != cI)
                        bulk_cp(bufA[nslot], (const char*)g_Fs + (size_t)pI * BLKB,
                                BLKB, mb[cur ^ 1]);
                    bulk_cp(bufB[cur ^ 1], (const char*)g_Fs + (size_t)pJ * BLKB,
                            BLKB, mb[cur ^ 1]);
                }
                compute_tile(bufA[ca], bufB[cur], cI, cJ);
                cI = pI; cJ = pJ; ca = nslot;
            } else {
                compute_tile(bufA[ca], bufB[cur], cI, cJ);
            }
        }
    }

    gbar(tid, target);

    // ---------------- Phase C: gather + deterministic final sum ----------------
    if (bx < 16) {
        double* sm = (double*)dynsmem;
        int row = bx * 512 + tid;
        int R = row >> 7, m = row & 127;
        float s = 0.f;
        #pragma unroll 8
        for (int O = 0; O < NBLK; O++)
            s += g_part[((size_t)R * NBLK + O) * 128 + m];
        sm[tid] = (double)(g_pos[row] - logf(s));
        __syncthreads();
        #pragma unroll
        for (int o = 256; o; o >>= 1) {
            if (tid < o) sm[tid] += sm[tid + o];
            __syncthreads();
        }
        __shared__ int isLast;
        if (tid == 0) {
            g_bsum[bx] = sm[0];
            __threadfence();
            isLast = (atomicAdd(&g_ctr, 1) == 15);
        }
        __syncthreads();
        if (isLast && tid == 0) {
            double tot = 0.0;
            #pragma unroll
            for (int i = 0; i < 16; i++) tot += g_bsum[i];
            out[0] = (float)(-tot / (double)TWO_N);
            g_ctr = 0;   // reset for graph replay
        }
    }
}

// ---------------------------------------------------------------------------
extern "C" void kernel_launch(void* const* d_in, const int* in_sizes, int n_in,
                              void* d_out, int out_size) {
    const float* f1 = (const float*)d_in[0];
    const float* f2 = (const float*)d_in[1];
    float* out = (float*)d_out;

    cudaFuncSetAttribute(ntxent_fused_kernel,
                         cudaFuncAttributeMaxDynamicSharedMemorySize, SMEM_DYN);

    ntxent_fused_kernel<<<GRID, 512, SMEM_DYN>>>(f1, f2, out);
}

// round 12
// speedup vs baseline: 1.2880x; 1.0406x over previous
#include <cuda_runtime.h>
#include <cuda_fp16.h>
#include <math.h>
#include <stdint.h>

// NT-Xent R12: amortize per-tile overhead. 128x256 tiles (one 64KB bulk copy
// for B, since g_Fs blocks are contiguous), warp tile 32x64, 512 threads.
// Halves the per-tile syncs/reductions/writeouts that R11 profiling showed
// dominate (tensor pipe idle 72%). Triangle at 256-col granularity: 1056 tiles.

#define TWO_N   8192
#define N_HALF  4096
#define CDIM    128
#define NBLK    64
#define TILES   1056
#define GRID    148
#define INV_T   14.285714285714286f
#define K1      20.60984248218323f           // INV_T * log2(e)
#define BLKB    32768                        // one 128-row fp16 block

#define OFF_A0  0
#define OFF_A1  BLKB
#define OFF_B0  (2 * BLKB)                   // 65536
#define OFF_B1  (4 * BLKB)                   // 131072
#define OFF_RED (6 * BLKB)                   // 196608
#define SMEM_DYN (OFF_RED + 128 * 5 * 4 + 256 * 5 * 4)   // 204288

__device__ __align__(128) __half g_Fs[TWO_N * CDIM];   // swizzled 128-row blocks
__device__ float g_part[NBLK * NBLK * 128];
__device__ float g_pos[TWO_N];
__device__ double g_bsum[16];
__device__ int g_ctr;
__device__ int g_sense;
__device__ int g_count;

__device__ __forceinline__ uint32_t smem_u32(const void* p) {
    uint32_t a;
    asm("{ .reg .u64 t; cvta.to.shared.u64 t, %1; cvt.u32.u64 %0, t; }"
        : "=r"(a) : "l"(p));
    return a;
}
__device__ __forceinline__ float ex2f(float x) {
    float r;
    asm("ex2.approx.ftz.f32 %0, %1;" : "=f"(r) : "f"(x));
    return r;
}
__device__ __forceinline__ void bulk_cp(uint32_t s, const void* g,
                                        uint32_t bytes, uint32_t mbar) {
    asm volatile(
        "cp.async.bulk.shared::cta.global.mbarrier::complete_tx::bytes "
        "[%0], [%1], %2, [%3];"
        :: "r"(s), "l"(g), "r"(bytes), "r"(mbar) : "memory");
}
#define MBAR_INIT(a, n) \
    asm volatile("mbarrier.init.shared.b64 [%0], %1;" :: "r"(a), "r"(n) : "memory")
#define MBAR_EXPECT(a, bytes) \
    asm volatile("mbarrier.arrive.expect_tx.shared.b64 _, [%0], %1;" \
                 :: "r"(a), "r"((uint32_t)(bytes)) : "memory")
#define MBAR_WAIT(a, ph) do {                                                  \
    uint32_t _m = (a), _p = (ph), _d;                                          \
    asm volatile("{\n\t.reg .pred p;\n\t"                                      \
        "mbarrier.try_wait.parity.acquire.cta.shared::cta.b64 p, [%1], %2;\n\t"\
        "selp.b32 %0, 1, 0, p;\n\t}"                                           \
        : "=r"(_d) : "r"(_m), "r"(_p) : "memory");                             \
    if (!_d) {                                                                 \
        asm volatile("{\n\t.reg .pred P1;\n\t"                                 \
            "W%=:\n\t"                                                         \
            "mbarrier.try_wait.parity.acquire.cta.shared::cta.b64 P1, [%0], %1, 0x989680;\n\t" \
            "@P1 bra.uni D%=;\n\t"                                             \
            "bra.uni W%=;\n\t"                                                 \
            "D%=:\n\t}" :: "r"(_m), "r"(_p) : "memory");                       \
    } } while (0)
#define FENCE_PROXY() asm volatile("fence.proxy.async;" ::: "memory")

#define LDSM_X4(r0, r1, r2, r3, addr)                                          \
    asm volatile("ldmatrix.sync.aligned.m8n8.x4.shared.b16 {%0,%1,%2,%3},[%4];"\
        : "=r"(r0), "=r"(r1), "=r"(r2), "=r"(r3) : "r"(addr))

#define MMA16816H(c, a, b0, b1)                                                \
    asm volatile("mma.sync.aligned.m16n8k16.row.col.f16.f16.f16.f16 "          \
        "{%0,%1},{%2,%3,%4,%5},{%6,%7},{%0,%1};"                               \
        : "+r"((c)[0]), "+r"((c)[1])                                           \
        : "r"((a)[0]), "r"((a)[1]), "r"((a)[2]), "r"((a)[3]),                  \
          "r"(b0), "r"(b1))

__device__ __forceinline__ void gbar(int tid, int& target) {
    __syncthreads();
    if (tid == 0) {
        __threadfence();
        if (atomicAdd(&g_count, 1) == GRID - 1) {
            g_count = 0;
            __threadfence();
            atomicAdd(&g_sense, 1);
        } else {
            while (((volatile int*)&g_sense)[0] - target < 0) {}
            __threadfence();
        }
    }
    __syncthreads();
    target++;
}

extern __shared__ char dynsmem[];

__global__ void __launch_bounds__(512, 1) ntxent_fused_kernel(
        const float* __restrict__ f1, const float* __restrict__ f2,
        float* __restrict__ out) {
    const int tid  = threadIdx.x;
    const int lane = tid & 31;
    const int wid  = tid >> 5;       // 0..15
    const int wm   = wid & 3;        // 4 m-warps x 32 rows
    const int wn   = wid >> 2;       // 4 n-warps x 64 cols
    const int bx   = blockIdx.x;

    __shared__ __align__(8) uint64_t s_mbar[2];
    __shared__ int sTgt;
    const uint32_t mb[2] = { smem_u32(&s_mbar[0]), smem_u32(&s_mbar[1]) };

    if (tid == 0) {
        sTgt = ((volatile int*)&g_sense)[0] + 1;
        MBAR_INIT(mb[0], 1);
        MBAR_INIT(mb[1], 1);
        FENCE_PROXY();
    }
    __syncthreads();
    int target = sTgt;

    // ---------------- Phase A: normalize + swizzled fp16 + pos ----------------
    for (int i = bx * 16 + wid; i < N_HALF; i += GRID * 16) {
        float4 a = *(const float4*)(f1 + (size_t)i * CDIM + lane * 4);
        float4 b = *(const float4*)(f2 + (size_t)i * CDIM + lane * 4);
        float s1 = a.x * a.x + a.y * a.y + a.z * a.z + a.w * a.w;
        float s2 = b.x * b.x + b.y * b.y + b.z * b.z + b.w * b.w;
        float d  = a.x * b.x + a.y * b.y + a.z * b.z + a.w * b.w;
        #pragma unroll
        for (int o = 16; o; o >>= 1) {
            s1 += __shfl_xor_sync(0xffffffffu, s1, o);
            s2 += __shfl_xor_sync(0xffffffffu, s2, o);
            d  += __shfl_xor_sync(0xffffffffu, d,  o);
        }
        float i1 = 1.0f / fmaxf(sqrtf(s1), 1e-12f);
        float i2 = 1.0f / fmaxf(sqrtf(s2), 1e-12f);

        int c16 = lane >> 1, hf = lane & 1;
        {
            int r = i & 127;
            uint32_t off = (uint32_t)(i >> 7) * BLKB + (uint32_t)r * 256
                         + (uint32_t)((c16 ^ (r & 7)) * 16) + (uint32_t)hf * 8;
            __half2 h0 = __floats2half2_rn(a.x * i1, a.y * i1);
            __half2 h1 = __floats2half2_rn(a.z * i1, a.w * i1);
            uint2 u; u.x = *(uint32_t*)&h0; u.y = *(uint32_t*)&h1;
            *(uint2*)((char*)g_Fs + off) = u;
        }
        {
            int j = i + N_HALF;
            int r = j & 127;
            uint32_t off = (uint32_t)(j >> 7) * BLKB + (uint32_t)r * 256
                         + (uint32_t)((c16 ^ (r & 7)) * 16) + (uint32_t)hf * 8;
            __half2 g0 = __floats2half2_rn(b.x * i2, b.y * i2);
            __half2 g1 = __floats2half2_rn(b.z * i2, b.w * i2);
            uint2 u; u.x = *(uint32_t*)&g0; u.y = *(uint32_t*)&g1;
            *(uint2*)((char*)g_Fs + off) = u;
        }
        if (lane == 0) {
            float pos = (d * i1 * i2 - 1.0f) * INV_T;
            g_pos[i] = pos;
            g_pos[i + N_HALF] = pos;
        }
    }

    gbar(tid, target);
    FENCE_PROXY();

    // ---------------- Phase B: HMMA 128x256 tiles ----------------
    {
        uint32_t sb = smem_u32(dynsmem);
        const uint32_t bufA[2] = { sb + OFF_A0, sb + OFF_A1 };
        const uint32_t bufB[2] = { sb + OFF_B0, sb + OFF_B1 };
        float* sRow = (float*)(dynsmem + OFF_RED);   // [128][5]
        float* sCol = sRow + 128 * 5;                // [256][5]

        const int rowA  = wm * 32 + (lane & 15);
        const int r7A   = rowA & 7;
        const int cbA   = lane >> 4;
        const uint32_t aRB = (uint32_t)rowA * 256;
        // B rows (= tile cols) for this warp: wn*64 + np*16 + rlowB
        const int rlowB = (lane & 7) + ((lane >> 4) & 1) * 8;
        const int cbB   = (lane >> 3) & 1;

        auto compute_tile = [&](uint32_t aBuf, uint32_t bBuf, int I, int J2) {
            const int Jblk  = 2 * J2 + (wn >> 1);     // this warp's 128-col block
            const bool active = (Jblk >= I);
            float pr[4], pc[16];
            #pragma unroll
            for (int h = 0; h < 4; h++) pr[h] = 0.f;
            #pragma unroll
            for (int h = 0; h < 16; h++) pc[h] = 0.f;

            if (active) {
                uint32_t acc[2][8][2];
                #pragma unroll
                for (int mi = 0; mi < 2; mi++)
                    #pragma unroll
                    for (int ni = 0; ni < 8; ni++) {
                        acc[mi][ni][0] = 0u; acc[mi][ni][1] = 0u;
                    }
                #pragma unroll
                for (int ks = 0; ks < 8; ks++) {
                    uint32_t afr[2][4], bfr[4][4];
                    const uint32_t aoff = (uint32_t)(((ks * 2 + cbA) ^ r7A) * 16);
                    #pragma unroll
                    for (int mi = 0; mi < 2; mi++) {
                        uint32_t ad = aBuf + aRB + (uint32_t)(mi * 16 * 256) + aoff;
                        LDSM_X4(afr[mi][0], afr[mi][1], afr[mi][2], afr[mi][3], ad);
                    }
                    #pragma unroll
                    for (int np = 0; np < 4; np++) {
                        int rB  = wn * 64 + np * 16 + rlowB;
                        uint32_t boff = (uint32_t)(((ks * 2 + cbB) ^ (rB & 7)) * 16);
                        uint32_t bd = bBuf + (uint32_t)rB * 256 + boff;
                        LDSM_X4(bfr[np][0], bfr[np][1], bfr[np][2], bfr[np][3], bd);
                    }
                    #pragma unroll
                    for (int mi = 0; mi < 2; mi++)
                        #pragma unroll
                        for (int ni = 0; ni < 8; ni++)
                            MMA16816H(acc[mi][ni], afr[mi],
                                      bfr[ni >> 1][(ni & 1) * 2],
                                      bfr[ni >> 1][(ni & 1) * 2 + 1]);
                }
                #pragma unroll
                for (int mi = 0; mi < 2; mi++)
                    #pragma unroll
                    for (int ni = 0; ni < 8; ni++)
                        #pragma unroll
                        for (int rg = 0; rg < 2; rg++) {
                            float2 f = __half22float2(*(const __half2*)&acc[mi][ni][rg]);
                            float e0 = ex2f(fmaf(f.x, K1, -K1));
                            float e1 = ex2f(fmaf(f.y, K1, -K1));
                            pr[mi * 2 + rg] += e0 + e1;
                            pc[ni * 2]     += e0;
                            pc[ni * 2 + 1] += e1;
                        }
                if (Jblk == I) {
                    #pragma unroll
                    for (int mi = 0; mi < 2; mi++)
                        #pragma unroll
                        for (int ni = 0; ni < 8; ni++)
                            #pragma unroll
                            for (int rg = 0; rg < 2; rg++) {
                                int rT = wm * 32 + mi * 16 + (lane >> 2) + 8 * rg;
                                int cB = (wn & 1) * 64 + ni * 8 + (lane & 3) * 2;
                                if (cB == rT || cB + 1 == rT) {
                                    float2 f = __half22float2(
                                        *(const __half2*)&acc[mi][ni][rg]);
                                    float fd = (cB == rT) ? f.x : f.y;
                                    pr[mi * 2 + rg] -= ex2f(fmaf(fd, K1, -K1));
                                }
                            }
                }
            }

            #pragma unroll
            for (int h = 0; h < 4; h++) {
                pr[h] += __shfl_xor_sync(0xffffffffu, pr[h], 1);
                pr[h] += __shfl_xor_sync(0xffffffffu, pr[h], 2);
            }
            #pragma unroll
            for (int h = 0; h < 16; h++) {
                pc[h] += __shfl_xor_sync(0xffffffffu, pc[h], 4);
                pc[h] += __shfl_xor_sync(0xffffffffu, pc[h], 8);
                pc[h] += __shfl_xor_sync(0xffffffffu, pc[h], 16);
            }
            if ((lane & 3) == 0) {
                #pragma unroll
                for (int h = 0; h < 4; h++) {
                    int r = wm * 32 + (h >> 1) * 16 + (lane >> 2) + 8 * (h & 1);
                    sRow[r * 5 + wn] = pr[h];
                }
            }
            if (lane < 4) {
                #pragma unroll
                for (int h = 0; h < 16; h++) {
                    int c = wn * 64 + (h >> 1) * 8 + lane * 2 + (h & 1);
                    sCol[c * 5 + wm] = pc[h];
                }
            }
            __syncthreads();

            const int JA = 2 * J2, JB = 2 * J2 + 1;
            if (tid < 128) {
                float vA = sRow[tid * 5 + 0] + sRow[tid * 5 + 1];
                float vB = sRow[tid * 5 + 2] + sRow[tid * 5 + 3];
                if (JA >= I) g_part[((size_t)I * NBLK + JA) * 128 + tid] = vA;
                g_part[((size_t)I * NBLK + JB) * 128 + tid] = vB;
            } else if (tid < 384) {
                int c  = tid - 128;
                int Jb = JA + (c >> 7);
                if (Jb > I)
                    g_part[((size_t)Jb * NBLK + I) * 128 + (c & 127)] =
                        sCol[c * 5] + sCol[c * 5 + 1] + sCol[c * 5 + 2] + sCol[c * 5 + 3];
            }
            __syncthreads();   // writeout + buffer reads complete
        };

        // Contiguous range of 256-col tiles.
        const int s = (int)(((long long)bx * TILES) / GRID);
        const int e = (int)(((long long)(bx + 1) * TILES) / GRID);
        int I = 0, rem = s;
        while (rem >= 32 - (I >> 1)) { rem -= 32 - (I >> 1); I++; }
        int J2 = (I >> 1) + rem;
        const int nt = e - s;

        int ph[2] = { 0, 0 };
        if (tid == 0) {
            MBAR_EXPECT(mb[0], BLKB + 2 * BLKB);
            bulk_cp(bufA[0], (const char*)g_Fs + (size_t)I * BLKB, BLKB, mb[0]);
            bulk_cp(bufB[0], (const char*)g_Fs + (size_t)J2 * 2 * BLKB,
                    2 * BLKB, mb[0]);
        }

        int cI = I, cJ = J2;
        int ca = 0;
        for (int t = 0; t < nt; t++) {
            const int cur = t & 1;
            MBAR_WAIT(mb[cur], ph[cur]); ph[cur] ^= 1;

            if (t + 1 < nt) {
                int pI = cI, pJ = cJ + 1;
                if (pJ == 32) { pI = cI + 1; pJ = pI >> 1; }
                int nslot = (pI != cI) ? (ca ^ 1) : ca;
                if (tid == 0) {
                    uint32_t bytes = (pI != cI) ? 3 * BLKB : 2 * BLKB;
                    MBAR_EXPECT(mb[cur ^ 1], bytes);
                    if (pI != cI)
                        bulk_cp(bufA[nslot], (const char*)g_Fs + (size_t)pI * BLKB,
                                BLKB, mb[cur ^ 1]);
                    bulk_cp(bufB[cur ^ 1], (const char*)g_Fs + (size_t)pJ * 2 * BLKB,
                            2 * BLKB, mb[cur ^ 1]);
                }
                compute_tile(bufA[ca], bufB[cur], cI, cJ);
                cI = pI; cJ = pJ; ca = nslot;
            } else {
                compute_tile(bufA[ca], bufB[cur], cI, cJ);
            }
        }
    }

    gbar(tid, target);

    // ---------------- Phase C: gather + deterministic final sum ----------------
    if (bx < 16) {
        double* sm = (double*)dynsmem;
        int row = bx * 512 + tid;
        int R = row >> 7, m = row & 127;
        float s = 0.f;
        #pragma unroll 8
        for (int O = 0; O < NBLK; O++)
            s += g_part[((size_t)R * NBLK + O) * 128 + m];
        sm[tid] = (double)(g_pos[row] - logf(s));
        __syncthreads();
        #pragma unroll
        for (int o = 256; o; o >>= 1) {
            if (tid < o) sm[tid] += sm[tid + o];
            __syncthreads();
        }
        __shared__ int isLast;
        if (tid == 0) {
            g_bsum[bx] = sm[0];
            __threadfence();
            isLast = (atomicAdd(&g_ctr, 1) == 15);
        }
        __syncthreads();
        if (isLast && tid == 0) {
            double tot = 0.0;
            #pragma unroll
            for (int i = 0; i < 16; i++) tot += g_bsum[i];
            out[0] = (float)(-tot / (double)TWO_N);
            g_ctr = 0;   // reset for graph replay
        }
    }
}

// ---------------------------------------------------------------------------
extern "C" void kernel_launch(void* const* d_in, const int* in_sizes, int n_in,
                              void* d_out, int out_size) {
    const float* f1 = (const float*)d_in[0];
    const float* f2 = (const float*)d_in[1];
    float* out = (float*)d_out;

    cudaFuncSetAttribute(ntxent_fused_kernel,
                         cudaFuncAttributeMaxDynamicSharedMemorySize, SMEM_DYN);

    ntxent_fused_kernel<<<GRID, 512, SMEM_DYN>>>(f1, f2, out);
}

// round 13
// speedup vs baseline: 1.4038x; 1.0899x over previous
#include <cuda_runtime.h>
#include <cuda_fp16.h>
#include <math.h>
#include <stdint.h>

// NT-Xent R13: two independent 256-thread CTAs per SM (grid 296) so the MUFU
// epilogue of one CTA overlaps the HMMA K-loop of the other (R12 profile:
// tensor idle 70% from per-tile phase lockstep). 128x128 tiles via bulk copy
// (A single-buffered, B double-buffered), triangle mapping (2080 tiles).

#define TWO_N   8192
#define N_HALF  4096
#define CDIM    128
#define NBLK    64
#define TILES   2080                         // 64*65/2
#define GRID    296                          // 2 CTAs per SM
#define INV_T   14.285714285714286f
#define K1      20.60984248218323f           // INV_T * log2(e)
#define BLKB    32768                        // one 128-row fp16 block

#define OFF_A   0
#define OFF_B0  BLKB
#define OFF_B1  (2 * BLKB)
#define OFF_RED (3 * BLKB)                   // 98304
#define SMEM_DYN (OFF_RED + 128 * 3 * 4 + 128 * 5 * 4)   // 102400

__device__ __align__(128) __half g_Fs[TWO_N * CDIM];   // swizzled 128-row blocks
__device__ float g_part[NBLK * NBLK * 128];
__device__ float g_pos[TWO_N];
__device__ double g_bsum[32];
__device__ int g_ctr;
__device__ int g_sense;
__device__ int g_count;

__device__ __forceinline__ uint32_t smem_u32(const void* p) {
    uint32_t a;
    asm("{ .reg .u64 t; cvta.to.shared.u64 t, %1; cvt.u32.u64 %0, t; }"
        : "=r"(a) : "l"(p));
    return a;
}
__device__ __forceinline__ float ex2f(float x) {
    float r;
    asm("ex2.approx.ftz.f32 %0, %1;" : "=f"(r) : "f"(x));
    return r;
}
__device__ __forceinline__ void bulk_cp(uint32_t s, const void* g,
                                        uint32_t bytes, uint32_t mbar) {
    asm volatile(
        "cp.async.bulk.shared::cta.global.mbarrier::complete_tx::bytes "
        "[%0], [%1], %2, [%3];"
        :: "r"(s), "l"(g), "r"(bytes), "r"(mbar) : "memory");
}
#define MBAR_INIT(a, n) \
    asm volatile("mbarrier.init.shared.b64 [%0], %1;" :: "r"(a), "r"(n) : "memory")
#define MBAR_EXPECT(a, bytes) \
    asm volatile("mbarrier.arrive.expect_tx.shared.b64 _, [%0], %1;" \
                 :: "r"(a), "r"((uint32_t)(bytes)) : "memory")
#define MBAR_WAIT(a, ph) do {                                                  \
    uint32_t _m = (a), _p = (ph), _d;                                          \
    asm volatile("{\n\t.reg .pred p;\n\t"                                      \
        "mbarrier.try_wait.parity.acquire.cta.shared::cta.b64 p, [%1], %2;\n\t"\
        "selp.b32 %0, 1, 0, p;\n\t}"                                           \
        : "=r"(_d) : "r"(_m), "r"(_p) : "memory");                             \
    if (!_d) {                                                                 \
        asm volatile("{\n\t.reg .pred P1;\n\t"                                 \
            "W%=:\n\t"                                                         \
            "mbarrier.try_wait.parity.acquire.cta.shared::cta.b64 P1, [%0], %1, 0x989680;\n\t" \
            "@P1 bra.uni D%=;\n\t"                                             \
            "bra.uni W%=;\n\t"                                                 \
            "D%=:\n\t}" :: "r"(_m), "r"(_p) : "memory");                       \
    } } while (0)
#define FENCE_PROXY() asm volatile("fence.proxy.async;" ::: "memory")

#define LDSM_X4(r0, r1, r2, r3, addr)                                          \
    asm volatile("ldmatrix.sync.aligned.m8n8.x4.shared.b16 {%0,%1,%2,%3},[%4];"\
        : "=r"(r0), "=r"(r1), "=r"(r2), "=r"(r3) : "r"(addr))

#define MMA16816H(c, a, b0, b1)                                                \
    asm volatile("mma.sync.aligned.m16n8k16.row.col.f16.f16.f16.f16 "          \
        "{%0,%1},{%2,%3,%4,%5},{%6,%7},{%0,%1};"                               \
        : "+r"((c)[0]), "+r"((c)[1])                                           \
        : "r"((a)[0]), "r"((a)[1]), "r"((a)[2]), "r"((a)[3]),                  \
          "r"(b0), "r"(b1))

__device__ __forceinline__ void gbar(int tid, int& target) {
    __syncthreads();
    if (tid == 0) {
        __threadfence();
        if (atomicAdd(&g_count, 1) == GRID - 1) {
            g_count = 0;
            __threadfence();
            atomicAdd(&g_sense, 1);
        } else {
            while (((volatile int*)&g_sense)[0] - target < 0) {}
            __threadfence();
        }
    }
    __syncthreads();
    target++;
}

extern __shared__ char dynsmem[];

__global__ void __launch_bounds__(256, 2) ntxent_fused_kernel(
        const float* __restrict__ f1, const float* __restrict__ f2,
        float* __restrict__ out) {
    const int tid  = threadIdx.x;
    const int lane = tid & 31;
    const int wid  = tid >> 5;       // 0..7
    const int wm   = wid & 3;        // 4 m-warps x 32 rows
    const int wn   = wid >> 2;       // 2 n-warps x 64 cols
    const int bx   = blockIdx.x;

    __shared__ __align__(8) uint64_t s_mbar[2];
    __shared__ int sTgt;
    const uint32_t mb[2] = { smem_u32(&s_mbar[0]), smem_u32(&s_mbar[1]) };

    if (tid == 0) {
        sTgt = ((volatile int*)&g_sense)[0] + 1;
        MBAR_INIT(mb[0], 1);
        MBAR_INIT(mb[1], 1);
        FENCE_PROXY();
    }
    __syncthreads();
    int target = sTgt;

    // ---------------- Phase A: normalize + swizzled fp16 + pos ----------------
    for (int i = bx * 8 + wid; i < N_HALF; i += GRID * 8) {
        float4 a = *(const float4*)(f1 + (size_t)i * CDIM + lane * 4);
        float4 b = *(const float4*)(f2 + (size_t)i * CDIM + lane * 4);
        float s1 = a.x * a.x + a.y * a.y + a.z * a.z + a.w * a.w;
        float s2 = b.x * b.x + b.y * b.y + b.z * b.z + b.w * b.w;
        float d  = a.x * b.x + a.y * b.y + a.z * b.z + a.w * b.w;
        #pragma unroll
        for (int o = 16; o; o >>= 1) {
            s1 += __shfl_xor_sync(0xffffffffu, s1, o);
            s2 += __shfl_xor_sync(0xffffffffu, s2, o);
            d  += __shfl_xor_sync(0xffffffffu, d,  o);
        }
        float i1 = 1.0f / fmaxf(sqrtf(s1), 1e-12f);
        float i2 = 1.0f / fmaxf(sqrtf(s2), 1e-12f);

        int c16 = lane >> 1, hf = lane & 1;
        {
            int r = i & 127;
            uint32_t off = (uint32_t)(i >> 7) * BLKB + (uint32_t)r * 256
                         + (uint32_t)((c16 ^ (r & 7)) * 16) + (uint32_t)hf * 8;
            __half2 h0 = __floats2half2_rn(a.x * i1, a.y * i1);
            __half2 h1 = __floats2half2_rn(a.z * i1, a.w * i1);
            uint2 u; u.x = *(uint32_t*)&h0; u.y = *(uint32_t*)&h1;
            *(uint2*)((char*)g_Fs + off) = u;
        }
        {
            int j = i + N_HALF;
            int r = j & 127;
            uint32_t off = (uint32_t)(j >> 7) * BLKB + (uint32_t)r * 256
                         + (uint32_t)((c16 ^ (r & 7)) * 16) + (uint32_t)hf * 8;
            __half2 g0 = __floats2half2_rn(b.x * i2, b.y * i2);
            __half2 g1 = __floats2half2_rn(b.z * i2, b.w * i2);
            uint2 u; u.x = *(uint32_t*)&g0; u.y = *(uint32_t*)&g1;
            *(uint2*)((char*)g_Fs + off) = u;
        }
        if (lane == 0) {
            float pos = (d * i1 * i2 - 1.0f) * INV_T;
            g_pos[i] = pos;
            g_pos[i + N_HALF] = pos;
        }
    }

    gbar(tid, target);
    FENCE_PROXY();

    // ---------------- Phase B: HMMA 128x128 tiles ----------------
    {
        uint32_t sb = smem_u32(dynsmem);
        const uint32_t bufA    = sb + OFF_A;
        const uint32_t bufB[2] = { sb + OFF_B0, sb + OFF_B1 };
        float* sRow = (float*)(dynsmem + OFF_RED);   // [128][3]
        float* sCol = sRow + 128 * 3;                // [128][5]

        const int rowA  = wm * 32 + (lane & 15);
        const int r7A   = rowA & 7;
        const int cbA   = lane >> 4;
        const uint32_t aRB = (uint32_t)rowA * 256;
        const int rlowB = (lane & 7) + ((lane >> 4) & 1) * 8;
        const int cbB   = (lane >> 3) & 1;

        auto compute_tile = [&](uint32_t bBuf, int I, int J) {
            float pr[4], pc[16];
            #pragma unroll
            for (int h = 0; h < 4; h++) pr[h] = 0.f;
            #pragma unroll
            for (int h = 0; h < 16; h++) pc[h] = 0.f;

            uint32_t acc[2][8][2];
            #pragma unroll
            for (int mi = 0; mi < 2; mi++)
                #pragma unroll
                for (int ni = 0; ni < 8; ni++) {
                    acc[mi][ni][0] = 0u; acc[mi][ni][1] = 0u;
                }
            #pragma unroll
            for (int ks = 0; ks < 8; ks++) {
                uint32_t afr[2][4], bfr[4][4];
                const uint32_t aoff = (uint32_t)(((ks * 2 + cbA) ^ r7A) * 16);
                #pragma unroll
                for (int mi = 0; mi < 2; mi++) {
                    uint32_t ad = bufA + aRB + (uint32_t)(mi * 16 * 256) + aoff;
                    LDSM_X4(afr[mi][0], afr[mi][1], afr[mi][2], afr[mi][3], ad);
                }
                #pragma unroll
                for (int np = 0; np < 4; np++) {
                    int rB  = wn * 64 + np * 16 + rlowB;
                    uint32_t boff = (uint32_t)(((ks * 2 + cbB) ^ (rB & 7)) * 16);
                    uint32_t bd = bBuf + (uint32_t)rB * 256 + boff;
                    LDSM_X4(bfr[np][0], bfr[np][1], bfr[np][2], bfr[np][3], bd);
                }
                #pragma unroll
                for (int mi = 0; mi < 2; mi++)
                    #pragma unroll
                    for (int ni = 0; ni < 8; ni++)
                        MMA16816H(acc[mi][ni], afr[mi],
                                  bfr[ni >> 1][(ni & 1) * 2],
                                  bfr[ni >> 1][(ni & 1) * 2 + 1]);
            }
            #pragma unroll
            for (int mi = 0; mi < 2; mi++)
                #pragma unroll
                for (int ni = 0; ni < 8; ni++)
                    #pragma unroll
                    for (int rg = 0; rg < 2; rg++) {
                        float2 f = __half22float2(*(const __half2*)&acc[mi][ni][rg]);
                        float e0 = ex2f(fmaf(f.x, K1, -K1));
                        float e1 = ex2f(fmaf(f.y, K1, -K1));
                        pr[mi * 2 + rg] += e0 + e1;
                        pc[ni * 2]     += e0;
                        pc[ni * 2 + 1] += e1;
                    }
            if (I == J) {
                #pragma unroll
                for (int mi = 0; mi < 2; mi++)
                    #pragma unroll
                    for (int ni = 0; ni < 8; ni++)
                        #pragma unroll
                        for (int rg = 0; rg < 2; rg++) {
                            int rT = wm * 32 + mi * 16 + (lane >> 2) + 8 * rg;
                            int cB = wn * 64 + ni * 8 + (lane & 3) * 2;
                            if (cB == rT || cB + 1 == rT) {
                                float2 f = __half22float2(
                                    *(const __half2*)&acc[mi][ni][rg]);
                                float fd = (cB == rT) ? f.x : f.y;
                                pr[mi * 2 + rg] -= ex2f(fmaf(fd, K1, -K1));
                            }
                        }
            }

            #pragma unroll
            for (int h = 0; h < 4; h++) {
                pr[h] += __shfl_xor_sync(0xffffffffu, pr[h], 1);
                pr[h] += __shfl_xor_sync(0xffffffffu, pr[h], 2);
            }
            #pragma unroll
            for (int h = 0; h < 16; h++) {
                pc[h] += __shfl_xor_sync(0xffffffffu, pc[h], 4);
                pc[h] += __shfl_xor_sync(0xffffffffu, pc[h], 8);
                pc[h] += __shfl_xor_sync(0xffffffffu, pc[h], 16);
            }
            if ((lane & 3) == 0) {
                #pragma unroll
                for (int h = 0; h < 4; h++) {
                    int r = wm * 32 + (h >> 1) * 16 + (lane >> 2) + 8 * (h & 1);
                    sRow[r * 3 + wn] = pr[h];
                }
            }
            if (lane < 4) {
                #pragma unroll
                for (int h = 0; h < 16; h++) {
                    int c = wn * 64 + (h >> 1) * 8 + lane * 2 + (h & 1);
                    sCol[c * 5 + wm] = pc[h];
                }
            }
            __syncthreads();

            if (tid < 128) {
                g_part[((size_t)I * NBLK + J) * 128 + tid] =
                    sRow[tid * 3] + sRow[tid * 3 + 1];
            } else {
                int c = tid - 128;
                if (J > I)
                    g_part[((size_t)J * NBLK + I) * 128 + c] =
                        sCol[c * 5] + sCol[c * 5 + 1] + sCol[c * 5 + 2] + sCol[c * 5 + 3];
            }
            __syncthreads();   // writeout + buffer reads complete
        };

        // Contiguous range of 128x128 tiles.
        const int s = (int)(((long long)bx * TILES) / GRID);
        const int e = (int)(((long long)(bx + 1) * TILES) / GRID);
        int I = 0, rem = s;
        while (rem >= NBLK - I) { rem -= NBLK - I; I++; }
        int J = I + rem;
        const int nt = e - s;

        int ph[2] = { 0, 0 };
        if (tid == 0) {
            MBAR_EXPECT(mb[0], 2 * BLKB);
            bulk_cp(bufA, (const char*)g_Fs + (size_t)I * BLKB, BLKB, mb[0]);
            bulk_cp(bufB[0], (const char*)g_Fs + (size_t)J * BLKB, BLKB, mb[0]);
        }

        int cI = I, cJ = J;
        for (int t = 0; t < nt; t++) {
            const int cur = t & 1;
            MBAR_WAIT(mb[cur], ph[cur]); ph[cur] ^= 1;

            const bool haveNext = (t + 1 < nt);
            int pI = cI, pJ = cJ + 1;
            if (pJ == NBLK) { pI = cI + 1; pJ = pI; }
            const bool newA = haveNext && (pI != cI);

            if (tid == 0 && haveNext) {
                MBAR_EXPECT(mb[cur ^ 1], newA ? 2 * BLKB : BLKB);
                bulk_cp(bufB[cur ^ 1], (const char*)g_Fs + (size_t)pJ * BLKB,
                        BLKB, mb[cur ^ 1]);
            }
            compute_tile(bufB[cur], cI, cJ);
            if (tid == 0 && newA) {
                FENCE_PROXY();   // order prior generic A-reads before async overwrite
                bulk_cp(bufA, (const char*)g_Fs + (size_t)pI * BLKB,
                        BLKB, mb[cur ^ 1]);
            }
            cI = pI; cJ = pJ;
        }
    }

    gbar(tid, target);

    // ---------------- Phase C: gather + deterministic final sum ----------------
    if (bx < 32) {
        double* sm = (double*)dynsmem;
        int row = bx * 256 + tid;
        int R = row >> 7, m = row & 127;
        float s = 0.f;
        #pragma unroll 8
        for (int O = 0; O < NBLK; O++)
            s += g_part[((size_t)R * NBLK + O) * 128 + m];
        sm[tid] = (double)(g_pos[row] - logf(s));
        __syncthreads();
        #pragma unroll
        for (int o = 128; o; o >>= 1) {
            if (tid < o) sm[tid] += sm[tid + o];
            __syncthreads();
        }
        __shared__ int isLast;
        if (tid == 0) {
            g_bsum[bx] = sm[0];
            __threadfence();
            isLast = (atomicAdd(&g_ctr, 1) == 31);
        }
        __syncthreads();
        if (isLast && tid == 0) {
            double tot = 0.0;
            #pragma unroll
            for (int i = 0; i < 32; i++) tot += g_bsum[i];
            out[0] = (float)(-tot / (double)TWO_N);
            g_ctr = 0;   // reset for graph replay
        }
    }
}

// ---------------------------------------------------------------------------
extern "C" void kernel_launch(void* const* d_in, const int* in_sizes, int n_in,
                              void* d_out, int out_size) {
    const float* f1 = (const float*)d_in[0];
    const float* f2 = (const float*)d_in[1];
    float* out = (float*)d_out;

    cudaFuncSetAttribute(ntxent_fused_kernel,
                         cudaFuncAttributeMaxDynamicSharedMemorySize, SMEM_DYN);

    ntxent_fused_kernel<<<GRID, 256, SMEM_DYN>>>(f1, f2, out);
}